// round 14
// baseline (speedup 1.0000x reference)
#include <cuda_runtime.h>
#include <cstdint>

#ifndef NEG_INF_F
#define NEG_INF_F __int_as_float(0xff800000)
#endif

// Strict-'>' insertion of (x, j) into the running sorted top-4.
// Values updated via a min/max (FMNMX, fma pipe) chain; indices via a
// select chain (alu pipe). Splitting across pipes doubles throughput vs
// an all-select ins4: the alu pipe was the measured bottleneck (58% busy).
// Equal x never displaces an incumbent (fmaxf keeps, c_i false) == the
// reference's smallest-edge-index tie-break. Non-improving x -> exact no-op.
__device__ __forceinline__ void ins4(float x, int j,
                                     float& v0, float& v1, float& v2, float& v3,
                                     int& i0, int& i1, int& i2, int& i3)
{
    bool c0 = x > v0;
    bool c1 = x > v1;
    bool c2 = x > v2;
    bool c3 = x > v3;
    i3 = c3 ? (c2 ? i2 : j) : i3;
    i2 = c2 ? (c1 ? i1 : j) : i2;
    i1 = c1 ? (c0 ? i0 : j) : i1;
    i0 = c0 ? j : i0;
    float m1 = fminf(v0, x);  v0 = fmaxf(v0, x);
    float m2 = fminf(v1, m1); v1 = fmaxf(v1, m1);
    float m3 = fminf(v2, m2); v2 = fmaxf(v2, m2);
    v3 = fmaxf(v3, m3);
}

__device__ __forceinline__ void ins_quad(float4 a, int j,
                                         float& v0, float& v1, float& v2, float& v3,
                                         int& i0, int& i1, int& i2, int& i3)
{
    ins4(a.x, j + 0, v0, v1, v2, v3, i0, i1, i2, i3);
    ins4(a.y, j + 1, v0, v1, v2, v3, i0, i1, i2, i3);
    ins4(a.z, j + 2, v0, v1, v2, v3, i0, i1, i2, i3);
    ins4(a.w, j + 3, v0, v1, v2, v3, i0, i1, i2, i3);
}

__device__ __forceinline__ float qmax(float4 a)
{
    return fmaxf(fmaxf(fmaxf(a.x, a.y), a.z), a.w);
}

// One thread per node. 8-edge body (2 x LDG.128 in flight), per-quad max
// fast-reject (exact under strict '>'), pipe-balanced insertion on hit.
__global__ void __launch_bounds__(256) segment_top4_kernel(
    const int* __restrict__ row_ptr,
    const float* __restrict__ scores,
    float* __restrict__ vals_out,   // [N,4] float32
    float* __restrict__ idxf_out,   // [N,4] float32 (index values; exact < 2^24)
    int n_nodes)
{
    int i = blockIdx.x * blockDim.x + threadIdx.x;
    if (i >= n_nodes) return;

    int s = __ldg(row_ptr + i);
    int e = __ldg(row_ptr + i + 1);

    float v0 = NEG_INF_F, v1 = NEG_INF_F, v2 = NEG_INF_F, v3 = NEG_INF_F;
    int   i0 = -1, i1 = -1, i2 = -1, i3 = -1;

    int j = s;

    // Scalar head to reach 16B alignment (scores base is 256B aligned).
    int head_end = (s + 3) & ~3;
    if (head_end > e) head_end = e;
    for (; j < head_end; ++j)
        ins4(__ldg(scores + j), j, v0, v1, v2, v3, i0, i1, i2, i3);

    const float4* sv = reinterpret_cast<const float4*>(scores);

    // 8-edge body: two LDG.128 per iteration.
    for (; j + 8 <= e; j += 8) {
        float4 a = __ldg(sv + (j >> 2));
        float4 b = __ldg(sv + (j >> 2) + 1);
        float ma = qmax(a);
        float mb = qmax(b);
        if (ma > v3) ins_quad(a, j,     v0, v1, v2, v3, i0, i1, i2, i3);
        if (mb > v3) ins_quad(b, j + 4, v0, v1, v2, v3, i0, i1, i2, i3);
    }
    if (j + 4 <= e) {
        float4 a = __ldg(sv + (j >> 2));
        if (qmax(a) > v3) ins_quad(a, j, v0, v1, v2, v3, i0, i1, i2, i3);
        j += 4;
    }

    // Scalar tail.
    for (; j < e; ++j)
        ins4(__ldg(scores + j), j, v0, v1, v2, v3, i0, i1, i2, i3);

    // Coalesced 16B vector stores.
    reinterpret_cast<float4*>(vals_out)[i] = make_float4(v0, v1, v2, v3);
    reinterpret_cast<float4*>(idxf_out)[i] =
        make_float4((float)i0, (float)i1, (float)i2, (float)i3);
}

extern "C" void kernel_launch(void* const* d_in, const int* in_sizes, int n_in,
                              void* d_out, int out_size)
{
    // row_ptr is the smaller input (N+1) vs edge_scores (E).
    int a = in_sizes[0], b = (n_in > 1) ? in_sizes[1] : 0;
    int rp_slot = (n_in > 1 && b < a) ? 1 : 0;
    const int*   row_ptr = (const int*)d_in[rp_slot];
    const float* scores  = (const float*)d_in[1 - rp_slot];
    long long n = (long long)in_sizes[rp_slot] - 1;

    // Single-dtype (float32) output: vals [N,4] then idx-as-float [N,4].
    float* vals_out = (float*)d_out;
    float* idxf_out = vals_out + n * 4;

    int threads = 256;
    int blocks = (int)((n + threads - 1) / threads);
    segment_top4_kernel<<<blocks, threads>>>(row_ptr, scores, vals_out, idxf_out, (int)n);
}

// round 15
// speedup vs baseline: 1.0615x; 1.0615x over previous
#include <cuda_runtime.h>
#include <cstdint>

#ifndef NEG_INF_F
#define NEG_INF_F __int_as_float(0xff800000)
#endif

// Branchless strict-'>' insertion of (x, j) into the running top-4.
// Value-only compares keep the incumbent on ties == reference's
// smallest-index tie-break. Non-improving x -> exact no-op.
__device__ __forceinline__ void ins4(float x, int j,
                                     float& v0, float& v1, float& v2, float& v3,
                                     int& i0, int& i1, int& i2, int& i3)
{
    bool c0 = x > v0;
    bool c1 = x > v1;
    bool c2 = x > v2;
    bool c3 = x > v3;
    v3 = c3 ? (c2 ? v2 : x) : v3;   i3 = c3 ? (c2 ? i2 : j) : i3;
    v2 = c2 ? (c1 ? v1 : x) : v2;   i2 = c2 ? (c1 ? i1 : j) : i2;
    v1 = c1 ? (c0 ? v0 : x) : v1;   i1 = c1 ? (c0 ? i0 : j) : i1;
    v0 = c0 ? x : v0;               i0 = c0 ? j : i0;
}

__device__ __forceinline__ void ins_quad(float4 a, int j,
                                         float& v0, float& v1, float& v2, float& v3,
                                         int& i0, int& i1, int& i2, int& i3)
{
    ins4(a.x, j + 0, v0, v1, v2, v3, i0, i1, i2, i3);
    ins4(a.y, j + 1, v0, v1, v2, v3, i0, i1, i2, i3);
    ins4(a.z, j + 2, v0, v1, v2, v3, i0, i1, i2, i3);
    ins4(a.w, j + 3, v0, v1, v2, v3, i0, i1, i2, i3);
}

__device__ __forceinline__ float qmax(float4 a)
{
    return fmaxf(fmaxf(fmaxf(a.x, a.y), a.z), a.w);
}

// Scan one node's segment [s, e) and write its outputs.
__device__ __forceinline__ void do_node(
    int i, const int* __restrict__ row_ptr, const float* __restrict__ scores,
    float* __restrict__ vals_out, float* __restrict__ idxf_out)
{
    int s = __ldg(row_ptr + i);
    int e = __ldg(row_ptr + i + 1);

    float v0 = NEG_INF_F, v1 = NEG_INF_F, v2 = NEG_INF_F, v3 = NEG_INF_F;
    int   i0 = -1, i1 = -1, i2 = -1, i3 = -1;

    int j = s;

    // Scalar head to reach 16B alignment (scores base is 256B aligned).
    int head_end = (s + 3) & ~3;
    if (head_end > e) head_end = e;
    for (; j < head_end; ++j)
        ins4(__ldg(scores + j), j, v0, v1, v2, v3, i0, i1, i2, i3);

    const float4* sv = reinterpret_cast<const float4*>(scores);

    // 8-edge body: two LDG.128 per iteration; per-quad max fast-reject
    // (exact under strict '>').
    for (; j + 8 <= e; j += 8) {
        float4 a = __ldg(sv + (j >> 2));
        float4 b = __ldg(sv + (j >> 2) + 1);
        float ma = qmax(a);
        float mb = qmax(b);
        if (ma > v3) ins_quad(a, j,     v0, v1, v2, v3, i0, i1, i2, i3);
        if (mb > v3) ins_quad(b, j + 4, v0, v1, v2, v3, i0, i1, i2, i3);
    }
    if (j + 4 <= e) {
        float4 a = __ldg(sv + (j >> 2));
        if (qmax(a) > v3) ins_quad(a, j, v0, v1, v2, v3, i0, i1, i2, i3);
        j += 4;
    }
    for (; j < e; ++j)
        ins4(__ldg(scores + j), j, v0, v1, v2, v3, i0, i1, i2, i3);

    // Coalesced 16B vector stores.
    reinterpret_cast<float4*>(vals_out)[i] = make_float4(v0, v1, v2, v3);
    reinterpret_cast<float4*>(idxf_out)[i] =
        make_float4((float)i0, (float)i1, (float)i2, (float)i3);
}

// Two adjacent nodes per thread: halves the grid to a single resident wave
// (977 blocks < 1184 concurrent at 8 blocks/SM) and smooths per-lane work
// (max-of-Poisson(64) imbalance 1.27x vs 1.4x at one node/thread).
__global__ void __launch_bounds__(256) segment_top4_kernel(
    const int* __restrict__ row_ptr,
    const float* __restrict__ scores,
    float* __restrict__ vals_out,   // [N,4] float32
    float* __restrict__ idxf_out,   // [N,4] float32 (index values; exact < 2^24)
    int n_nodes)
{
    int t = blockIdx.x * blockDim.x + threadIdx.x;
    int node = 2 * t;
    if (node >= n_nodes) return;

    do_node(node, row_ptr, scores, vals_out, idxf_out);
    if (node + 1 < n_nodes)
        do_node(node + 1, row_ptr, scores, vals_out, idxf_out);
}

extern "C" void kernel_launch(void* const* d_in, const int* in_sizes, int n_in,
                              void* d_out, int out_size)
{
    // row_ptr is the smaller input (N+1) vs edge_scores (E).
    int a = in_sizes[0], b = (n_in > 1) ? in_sizes[1] : 0;
    int rp_slot = (n_in > 1 && b < a) ? 1 : 0;
    const int*   row_ptr = (const int*)d_in[rp_slot];
    const float* scores  = (const float*)d_in[1 - rp_slot];
    long long n = (long long)in_sizes[rp_slot] - 1;

    // Single-dtype (float32) output: vals [N,4] then idx-as-float [N,4].
    float* vals_out = (float*)d_out;
    float* idxf_out = vals_out + n * 4;

    int threads = 256;
    long long n_threads_needed = (n + 1) / 2;
    int blocks = (int)((n_threads_needed + threads - 1) / threads);
    segment_top4_kernel<<<blocks, threads>>>(row_ptr, scores, vals_out, idxf_out, (int)n);
}

// round 16
// speedup vs baseline: 1.1310x; 1.0655x over previous
#include <cuda_runtime.h>
#include <cstdint>

#ifndef NEG_INF_F
#define NEG_INF_F __int_as_float(0xff800000)
#endif

// Compare-exchange, descending, strict (swap only if right strictly greater).
// Adjacent-only networks built from this are STABLE: equal values keep their
// original (smaller-index-first) order, matching the reference tie-break.
__device__ __forceinline__ void ce(float& va, int& ia, float& vb, int& ib)
{
    bool sw = vb > va;
    float tv = sw ? vb : va;  vb = sw ? va : vb;  va = tv;
    int   ti = sw ? ib : ia;  ib = sw ? ia : ib;  ia = ti;
}

// Scalar strict-'>' insertion (head/tail edges). Branchless select chain.
__device__ __forceinline__ void ins4(float x, int j,
                                     float& v0, float& v1, float& v2, float& v3,
                                     int& i0, int& i1, int& i2, int& i3)
{
    bool c0 = x > v0;
    bool c1 = x > v1;
    bool c2 = x > v2;
    bool c3 = x > v3;
    v3 = c3 ? (c2 ? v2 : x) : v3;   i3 = c3 ? (c2 ? i2 : j) : i3;
    v2 = c2 ? (c1 ? v1 : x) : v2;   i2 = c2 ? (c1 ? i1 : j) : i2;
    v1 = c1 ? (c0 ? v0 : x) : v1;   i1 = c1 ? (c0 ? i0 : j) : i1;
    v0 = c0 ? x : v0;               i0 = c0 ? j : i0;
}

// Merge one quad (4 consecutive edges) into the sorted top-4 accumulator.
// Unconditional straight-line network (no divergent branches):
//  1. stable bubble-sort the quad descending          (6 c-e)
//  2. bitonic select m_i = max_pref_acc(v_i, q_{3-i}) (4 sel) -> top-4 multiset
//  3. bitonic sort-4 of the (bitonic) m sequence      (4 c-e)
// Prefer-accumulator on value ties == strict-'>' insertion semantics
// (accumulator indices always precede quad indices).
__device__ __forceinline__ void quad_merge(float4 a, int j,
                                           float& v0, float& v1, float& v2, float& v3,
                                           int& i0, int& i1, int& i2, int& i3)
{
    float q0 = a.x, q1 = a.y, q2 = a.z, q3 = a.w;
    int   j0 = j, j1 = j + 1, j2 = j + 2, j3 = j + 3;

    // Stable sort descending (adjacent network).
    ce(q0, j0, q1, j1); ce(q1, j1, q2, j2); ce(q2, j2, q3, j3);
    ce(q0, j0, q1, j1); ce(q1, j1, q2, j2);
    ce(q0, j0, q1, j1);

    // Bitonic selection of the top-4 of the union (keep acc on ties).
    bool t0 = q3 > v0; float m0 = t0 ? q3 : v0; int n0 = t0 ? j3 : i0;
    bool t1 = q2 > v1; float m1 = t1 ? q2 : v1; int n1 = t1 ? j2 : i1;
    bool t2 = q1 > v2; float m2 = t2 ? q1 : v2; int n2 = t2 ? j1 : i2;
    bool t3 = q0 > v3; float m3 = t3 ? q0 : v3; int n3 = t3 ? j0 : i3;

    // Sort the bitonic sequence descending.
    ce(m0, n0, m2, n2); ce(m1, n1, m3, n3);
    ce(m0, n0, m1, n1); ce(m2, n2, m3, n3);

    v0 = m0; v1 = m1; v2 = m2; v3 = m3;
    i0 = n0; i1 = n1; i2 = n2; i3 = n3;
}

// One thread per node. 8-edge body: two LDG.128 front-batched, then two
// unconditional quad merges (lockstep-uniform, branch-free hot loop).
__global__ void __launch_bounds__(256) segment_top4_kernel(
    const int* __restrict__ row_ptr,
    const float* __restrict__ scores,
    float* __restrict__ vals_out,   // [N,4] float32
    float* __restrict__ idxf_out,   // [N,4] float32 (index values; exact < 2^24)
    int n_nodes)
{
    int i = blockIdx.x * blockDim.x + threadIdx.x;
    if (i >= n_nodes) return;

    int s = __ldg(row_ptr + i);
    int e = __ldg(row_ptr + i + 1);

    float v0 = NEG_INF_F, v1 = NEG_INF_F, v2 = NEG_INF_F, v3 = NEG_INF_F;
    int   i0 = -1, i1 = -1, i2 = -1, i3 = -1;

    int j = s;

    // Scalar head to reach 16B alignment (scores base is 256B aligned).
    int head_end = (s + 3) & ~3;
    if (head_end > e) head_end = e;
    for (; j < head_end; ++j)
        ins4(__ldg(scores + j), j, v0, v1, v2, v3, i0, i1, i2, i3);

    const float4* sv = reinterpret_cast<const float4*>(scores);

    // 8-edge body.
    for (; j + 8 <= e; j += 8) {
        float4 a = __ldg(sv + (j >> 2));
        float4 b = __ldg(sv + (j >> 2) + 1);
        quad_merge(a, j,     v0, v1, v2, v3, i0, i1, i2, i3);
        quad_merge(b, j + 4, v0, v1, v2, v3, i0, i1, i2, i3);
    }
    if (j + 4 <= e) {
        float4 a = __ldg(sv + (j >> 2));
        quad_merge(a, j, v0, v1, v2, v3, i0, i1, i2, i3);
        j += 4;
    }

    // Scalar tail.
    for (; j < e; ++j)
        ins4(__ldg(scores + j), j, v0, v1, v2, v3, i0, i1, i2, i3);

    // Coalesced 16B vector stores.
    reinterpret_cast<float4*>(vals_out)[i] = make_float4(v0, v1, v2, v3);
    reinterpret_cast<float4*>(idxf_out)[i] =
        make_float4((float)i0, (float)i1, (float)i2, (float)i3);
}

extern "C" void kernel_launch(void* const* d_in, const int* in_sizes, int n_in,
                              void* d_out, int out_size)
{
    // row_ptr is the smaller input (N+1) vs edge_scores (E).
    int a = in_sizes[0], b = (n_in > 1) ? in_sizes[1] : 0;
    int rp_slot = (n_in > 1 && b < a) ? 1 : 0;
    const int*   row_ptr = (const int*)d_in[rp_slot];
    const float* scores  = (const float*)d_in[1 - rp_slot];
    long long n = (long long)in_sizes[rp_slot] - 1;

    // Single-dtype (float32) output: vals [N,4] then idx-as-float [N,4].
    float* vals_out = (float*)d_out;
    float* idxf_out = vals_out + n * 4;

    int threads = 256;
    int blocks = (int)((n + threads - 1) / threads);
    segment_top4_kernel<<<blocks, threads>>>(row_ptr, scores, vals_out, idxf_out, (int)n);
}

// round 17
// speedup vs baseline: 1.1430x; 1.0106x over previous
#include <cuda_runtime.h>
#include <cstdint>

#define NEG_INF_F __int_as_float(0xff800000)

// Value-only compare-exchange, descending: 2 FMNMX, no predicate/select.
__device__ __forceinline__ void ce_v(float& a, float& b)
{
    float mx = fmaxf(a, b);
    float mn = fminf(a, b);
    a = mx; b = mn;
}

// 5-comparator sorting network, descending, values only.
__device__ __forceinline__ void sort4v(float& a0, float& a1, float& a2, float& a3)
{
    ce_v(a0, a1); ce_v(a2, a3);
    ce_v(a0, a2); ce_v(a1, a3);
    ce_v(a1, a2);
}

// Tagged compare-exchange (accumulator only): values via FMNMX, tags via SEL.
__device__ __forceinline__ void ce_t(float& a, int& ta, float& b, int& tb)
{
    bool sw = b > a;
    float mx = fmaxf(a, b);
    float mn = fminf(a, b);
    a = mx; b = mn;
    int x = sw ? tb : ta;
    tb = sw ? ta : tb;
    ta = x;
}

// Merge two sorted-desc 4-lists (values only), keep top-4 sorted desc in a.
__device__ __forceinline__ void merge44v(float& a0, float& a1, float& a2, float& a3,
                                         float b0, float b1, float b2, float b3)
{
    float m0 = fmaxf(a0, b3);
    float m1 = fmaxf(a1, b2);
    float m2 = fmaxf(a2, b1);
    float m3 = fmaxf(a3, b0);
    ce_v(m0, m2); ce_v(m1, m3);   // bitonic sort-4
    ce_v(m0, m1); ce_v(m2, m3);
    a0 = m0; a1 = m1; a2 = m2; a3 = m3;
}

// Merge a sorted-desc group top-4 (all tagged gj) into the tagged accumulator.
// Prefer-acc on value ties == reference's earlier-index tie-break.
__device__ __forceinline__ void merge_acc(
    float& v0, float& v1, float& v2, float& v3,
    int& t0, int& t1, int& t2, int& t3,
    float g0, float g1, float g2, float g3, int gj)
{
    bool c0 = g3 > v0; float m0 = c0 ? g3 : v0; int n0 = c0 ? gj : t0;
    bool c1 = g2 > v1; float m1 = c1 ? g2 : v1; int n1 = c1 ? gj : t1;
    bool c2 = g1 > v2; float m2 = c2 ? g1 : v2; int n2 = c2 ? gj : t2;
    bool c3 = g0 > v3; float m3 = c3 ? g0 : v3; int n3 = c3 ? gj : t3;
    ce_t(m0, n0, m2, n2); ce_t(m1, n1, m3, n3);
    ce_t(m0, n0, m1, n1); ce_t(m2, n2, m3, n3);
    v0 = m0; v1 = m1; v2 = m2; v3 = m3;
    t0 = n0; t1 = n1; t2 = n2; t3 = n3;
}

// Process one 8-edge pair at base j (4-aligned). MASK: apply [s,e) bounds.
template <bool MASK>
__device__ __forceinline__ void do_pair(
    const float4* __restrict__ sv, int j, int s, int e,
    float& v0, float& v1, float& v2, float& v3,
    int& t0, int& t1, int& t2, int& t3)
{
    float4 A = __ldg(sv + (j >> 2));
    float4 B;
    if (!MASK || (j + 4 < e)) B = __ldg(sv + (j >> 2) + 1);
    else B = make_float4(NEG_INF_F, NEG_INF_F, NEG_INF_F, NEG_INF_F);

    if (MASK) {
        A.x = (j + 0 >= s && j + 0 < e) ? A.x : NEG_INF_F;
        A.y = (j + 1 >= s && j + 1 < e) ? A.y : NEG_INF_F;
        A.z = (j + 2 >= s && j + 2 < e) ? A.z : NEG_INF_F;
        A.w = (j + 3 >= s && j + 3 < e) ? A.w : NEG_INF_F;
        B.x = (j + 4 < e) ? B.x : NEG_INF_F;   // lower bound always holds for B
        B.y = (j + 5 < e) ? B.y : NEG_INF_F;
        B.z = (j + 6 < e) ? B.z : NEG_INF_F;
        B.w = (j + 7 < e) ? B.w : NEG_INF_F;
    }

    sort4v(A.x, A.y, A.z, A.w);
    sort4v(B.x, B.y, B.z, B.w);
    merge44v(A.x, A.y, A.z, A.w, B.x, B.y, B.z, B.w);
    merge_acc(v0, v1, v2, v3, t0, t1, t2, t3, A.x, A.y, A.z, A.w, j);
}

// Recover the exact edge index of value v within the 8-edge group at `tag`,
// skipping `occ` earlier matches (duplicate handling). Masked same as scan.
__device__ __forceinline__ int recover(
    const float4* __restrict__ sv, int tag, float v, int s, int e, int occ)
{
    float4 A = __ldg(sv + (tag >> 2));
    float4 B;
    if (tag + 4 < e) B = __ldg(sv + (tag >> 2) + 1);
    else B = make_float4(NEG_INF_F, NEG_INF_F, NEG_INF_F, NEG_INF_F);

    float x0 = A.x, x1 = A.y, x2 = A.z, x3 = A.w;
    float x4 = B.x, x5 = B.y, x6 = B.z, x7 = B.w;

    int idx = -1;
    #pragma unroll
    for (int p = 0; p < 8; p++) {
        float xp = (p == 0) ? x0 : (p == 1) ? x1 : (p == 2) ? x2 : (p == 3) ? x3
                 : (p == 4) ? x4 : (p == 5) ? x5 : (p == 6) ? x6 : x7;
        int jj = tag + p;
        bool m = (xp == v) && (jj >= s) && (jj < e);
        if (m) {
            if (occ == 0 && idx < 0) idx = jj;
            occ--;
        }
    }
    return idx;
}

__global__ void __launch_bounds__(256) segment_top4_kernel(
    const int* __restrict__ row_ptr,
    const float* __restrict__ scores,
    float* __restrict__ vals_out,   // [N,4] float32
    float* __restrict__ idxf_out,   // [N,4] float32 (index values; exact < 2^24)
    int n_nodes)
{
    int i = blockIdx.x * blockDim.x + threadIdx.x;
    if (i >= n_nodes) return;

    int s = __ldg(row_ptr + i);
    int e = __ldg(row_ptr + i + 1);

    float v0 = NEG_INF_F, v1 = NEG_INF_F, v2 = NEG_INF_F, v3 = NEG_INF_F;
    int   t0 = -1, t1 = -1, t2 = -1, t3 = -1;

    const float4* sv = reinterpret_cast<const float4*>(scores);

    if (s < e) {
        int j = s & ~3;                  // 16B-aligned pair base
        // First pair: masked on both bounds.
        do_pair<true>(sv, j, s, e, v0, v1, v2, v3, t0, t1, t2, t3);
        j += 8;
        // Middle full pairs: branch-free masks, unconditional loads.
        for (; j + 8 <= e; j += 8)
            do_pair<false>(sv, j, s, e, v0, v1, v2, v3, t0, t1, t2, t3);
        // Last partial pair: masked on upper bound.
        if (j < e)
            do_pair<true>(sv, j, s, e, v0, v1, v2, v3, t0, t1, t2, t3);
    }

    // Index recovery: occurrence rank among earlier slots with same (tag, val).
    int o1 = (int)(t1 == t0 && v1 == v0);
    int o2 = (int)(t2 == t0 && v2 == v0) + (int)(t2 == t1 && v2 == v1);
    int o3 = (int)(t3 == t0 && v3 == v0) + (int)(t3 == t1 && v3 == v1)
           + (int)(t3 == t2 && v3 == v2);

    int i0 = (t0 >= 0) ? recover(sv, t0, v0, s, e, 0)  : -1;
    int i1 = (t1 >= 0) ? recover(sv, t1, v1, s, e, o1) : -1;
    int i2 = (t2 >= 0) ? recover(sv, t2, v2, s, e, o2) : -1;
    int i3 = (t3 >= 0) ? recover(sv, t3, v3, s, e, o3) : -1;

    // Coalesced 16B vector stores.
    reinterpret_cast<float4*>(vals_out)[i] = make_float4(v0, v1, v2, v3);
    reinterpret_cast<float4*>(idxf_out)[i] =
        make_float4((float)i0, (float)i1, (float)i2, (float)i3);
}

extern "C" void kernel_launch(void* const* d_in, const int* in_sizes, int n_in,
                              void* d_out, int out_size)
{
    // row_ptr is the smaller input (N+1) vs edge_scores (E).
    int a = in_sizes[0], b = (n_in > 1) ? in_sizes[1] : 0;
    int rp_slot = (n_in > 1 && b < a) ? 1 : 0;
    const int*   row_ptr = (const int*)d_in[rp_slot];
    const float* scores  = (const float*)d_in[1 - rp_slot];
    long long n = (long long)in_sizes[rp_slot] - 1;

    // Single-dtype (float32) output: vals [N,4] then idx-as-float [N,4].
    float* vals_out = (float*)d_out;
    float* idxf_out = vals_out + n * 4;

    int threads = 256;
    int blocks = (int)((n + threads - 1) / threads);
    segment_top4_kernel<<<blocks, threads>>>(row_ptr, scores, vals_out, idxf_out, (int)n);
}